// round 10
// baseline (speedup 1.0000x reference)
#include <cuda_runtime.h>
#include <stdint.h>

#define NN 100000
#define F  64
#define E_MAX 1700000

// ---- scratch (static __device__ arrays; no allocation allowed) ----
__device__ int   g_cnt[NN];          // in-degree (real edges only)
__device__ float g_dis[NN];          // deg^{-1/2} (incl. self loop)
__device__ int   g_rowptr[NN + 1];
__device__ int   g_cursor[NN];
__device__ int2  g_csr[E_MAX];       // {src, float_as_int(norm)} grouped by dst
__device__ float g_h[NN * F];        // linear output of current layer
__device__ float g_agg[NN * F];      // layer-1 aggregation result
__device__ int   g_is64;             // edge_index dtype flag

// ---------------------------------------------------------------------------
// K0: detect edge_index dtype. For nonnegative int64 (LE), every odd 32-bit
// word is 0. For random int32 indices, essentially never.
__global__ void k_detect(const unsigned int* __restrict__ w) {
    if (threadIdx.x == 0 && blockIdx.x == 0) {
        int is64 = 1;
        #pragma unroll 1
        for (int i = 1; i < 128; i += 2)
            if (w[i] != 0u) { is64 = 0; break; }
        g_is64 = is64;
    }
}

__device__ __forceinline__ int load_idx(const void* ei, long long elem, int is64) {
    if (is64) return (int)((const long long*)ei)[elem];
    return ((const int*)ei)[elem];
}

// K1: zero in-degree counters
__global__ void k_cnt_init(int* cnt, int n) {
    int i = blockIdx.x * blockDim.x + threadIdx.x;
    if (i < n) cnt[i] = 0;
}

// K2: in-degree histogram over real edges (dst row of edge_index [2,E])
__global__ void k_cnt_acc(const void* __restrict__ ei, int* cnt, int E) {
    int e = blockIdx.x * blockDim.x + threadIdx.x;
    if (e >= E) return;
    int d = load_idx(ei, (long long)E + e, g_is64);
    if ((unsigned)d < (unsigned)NN) atomicAdd(&cnt[d], 1);
}

// K3: dis = (cnt+1)^{-1/2}   (+1 self loop)
__global__ void k_dis(const int* __restrict__ cnt, float* dis, int n) {
    int i = blockIdx.x * blockDim.x + threadIdx.x;
    if (i < n) dis[i] = rsqrtf((float)cnt[i] + 1.0f);
}

// K4: exclusive scan of cnt -> rowptr (and cursor copy). One block.
__global__ void k_scan(const int* __restrict__ cnt, int* __restrict__ rowptr,
                       int* __restrict__ cursor, int n) {
    __shared__ int warp_tot[32];
    const int T = blockDim.x;            // 1024
    int tid  = threadIdx.x;
    int per  = (n + T - 1) / T;
    int start = tid * per;
    int end   = min(start + per, n);

    int sum = 0;
    for (int i = start; i < end; i++) sum += cnt[i];

    // block-wide exclusive scan of per-thread sums
    int lane = tid & 31, warp = tid >> 5;
    int v = sum;
    #pragma unroll
    for (int o = 1; o < 32; o <<= 1) {
        int t = __shfl_up_sync(0xffffffffu, v, o);
        if (lane >= o) v += t;
    }
    if (lane == 31) warp_tot[warp] = v;
    __syncthreads();
    if (warp == 0) {
        int wv = (lane < 32) ? warp_tot[lane] : 0;
        #pragma unroll
        for (int o = 1; o < 32; o <<= 1) {
            int t = __shfl_up_sync(0xffffffffu, wv, o);
            if (lane >= o) wv += t;
        }
        warp_tot[lane] = wv;
    }
    __syncthreads();
    int excl = v - sum + (warp > 0 ? warp_tot[warp - 1] : 0);

    int off = excl;
    for (int i = start; i < end; i++) {
        rowptr[i] = off;
        cursor[i] = off;
        off += cnt[i];
    }
    if (end == n && start < n) rowptr[n] = off;
    if (n <= start && tid == T - 1) rowptr[n] = warp_tot[31]; // degenerate safety
}

// K5: fill CSR — slot per edge via cursor atomic; store {src, norm}
__global__ void k_fill(const void* __restrict__ ei, const float* __restrict__ dis,
                       int* __restrict__ cursor, int2* __restrict__ csr, int E) {
    int e = blockIdx.x * blockDim.x + threadIdx.x;
    if (e >= E) return;
    int is64 = g_is64;
    int s = load_idx(ei, e, is64);
    int d = load_idx(ei, (long long)E + e, is64);
    if ((unsigned)s >= (unsigned)NN || (unsigned)d >= (unsigned)NN) return;
    float nm = dis[s] * dis[d];
    int slot = atomicAdd(&cursor[d], 1);
    csr[slot] = make_int2(s, __float_as_int(nm));
}

// ---------------------------------------------------------------------------
// GEMM: H[n,64] = act(X[n,64]) @ W[64,64]. Warp-per-row, W in smem,
// x row in registers (float2/lane), shfl broadcast.
__global__ void k_gemm64(const float* __restrict__ X, const float* __restrict__ Wg,
                         float* __restrict__ H, int n, int do_relu) {
    __shared__ __align__(16) float Ws[F * F];
    for (int i = threadIdx.x; i < F * F; i += blockDim.x) Ws[i] = Wg[i];
    __syncthreads();

    int warp = (blockIdx.x * blockDim.x + threadIdx.x) >> 5;
    int lane = threadIdx.x & 31;
    if (warp >= n) return;

    float2 xv = ((const float2*)(X + (size_t)warp * F))[lane];
    if (do_relu) { xv.x = fmaxf(xv.x, 0.0f); xv.y = fmaxf(xv.y, 0.0f); }

    float a0 = 0.0f, a1 = 0.0f;
#pragma unroll
    for (int k = 0; k < F; k++) {
        float xk = __shfl_sync(0xffffffffu, (k & 1) ? xv.y : xv.x, k >> 1);
        float2 w = ((const float2*)(Ws + k * F))[lane];
        a0 = fmaf(xk, w.x, a0);
        a1 = fmaf(xk, w.y, a1);
    }
    ((float2*)(H + (size_t)warp * F))[lane] = make_float2(a0, a1);
}

// ---------------------------------------------------------------------------
// Gather-aggregate: warp per dst node. acc = H[node]*dis^2 + b, then
// += sum over incoming edges of H[src]*norm. Register accumulation, no atomics.
__global__ void k_gather(const int* __restrict__ rowptr, const int2* __restrict__ csr,
                         const float* __restrict__ H, const float* __restrict__ dis,
                         const float* __restrict__ b, float* __restrict__ Agg, int n) {
    int node = (blockIdx.x * blockDim.x + threadIdx.x) >> 5;
    int lane = threadIdx.x & 31;
    if (node >= n) return;

    int beg = rowptr[node];
    int end = rowptr[node + 1];

    float dd = dis[node];
    float sl = dd * dd;
    float2 hs = ((const float2*)(H + (size_t)node * F))[lane];
    float2 bb = ((const float2*)b)[lane];
    float ax = fmaf(hs.x, sl, bb.x);
    float ay = fmaf(hs.y, sl, bb.y);

    int j = beg;
    // 2-way unrolled mainloop to expose gather MLP
    for (; j + 1 < end; j += 2) {
        int2 e0 = __ldg(&csr[j]);
        int2 e1 = __ldg(&csr[j + 1]);
        float2 v0 = ((const float2*)(H + (size_t)e0.x * F))[lane];
        float2 v1 = ((const float2*)(H + (size_t)e1.x * F))[lane];
        float n0 = __int_as_float(e0.y);
        float n1 = __int_as_float(e1.y);
        ax = fmaf(v0.x, n0, ax);
        ay = fmaf(v0.y, n0, ay);
        ax = fmaf(v1.x, n1, ax);
        ay = fmaf(v1.y, n1, ay);
    }
    if (j < end) {
        int2 e0 = __ldg(&csr[j]);
        float2 v0 = ((const float2*)(H + (size_t)e0.x * F))[lane];
        float n0 = __int_as_float(e0.y);
        ax = fmaf(v0.x, n0, ax);
        ay = fmaf(v0.y, n0, ay);
    }
    ((float2*)(Agg + (size_t)node * F))[lane] = make_float2(ax, ay);
}

// ---------------------------------------------------------------------------
static inline int cdiv(int a, int b) { return (a + b - 1) / b; }

extern "C" void kernel_launch(void* const* d_in, const int* in_sizes, int n_in,
                              void* d_out, int out_size) {
    const float* x  = (const float*)d_in[0];
    const void*  ei = d_in[1];
    const float* W1 = (const float*)d_in[2];
    const float* b1 = (const float*)d_in[3];
    const float* W2 = (const float*)d_in[4];
    const float* b2 = (const float*)d_in[5];
    float*       out = (float*)d_out;

    const int N = in_sizes[0] / F;        // 100000
    const int E = in_sizes[1] / 2;        // 1600000

    int *cnt, *rowptr, *cursor;
    int2 *csr;
    float *dis, *h, *agg;
    cudaGetSymbolAddress((void**)&cnt,    g_cnt);
    cudaGetSymbolAddress((void**)&dis,    g_dis);
    cudaGetSymbolAddress((void**)&rowptr, g_rowptr);
    cudaGetSymbolAddress((void**)&cursor, g_cursor);
    cudaGetSymbolAddress((void**)&csr,    g_csr);
    cudaGetSymbolAddress((void**)&h,      g_h);
    cudaGetSymbolAddress((void**)&agg,    g_agg);

    const int T = 256;

    // ---- preprocessing (once per call, reused by both layers) ----
    k_detect  <<<1, 32>>>((const unsigned int*)ei);
    k_cnt_init<<<cdiv(N, T), T>>>(cnt, N);
    k_cnt_acc <<<cdiv(E, T), T>>>(ei, cnt, E);
    k_dis     <<<cdiv(N, T), T>>>(cnt, dis, N);
    k_scan    <<<1, 1024>>>(cnt, rowptr, cursor, N);
    k_fill    <<<cdiv(E, T), T>>>(ei, dis, cursor, csr, E);

    // ---- layer 1 ----
    k_gemm64  <<<cdiv(N * 32, T), T>>>(x, W1, h, N, 0);
    k_gather  <<<cdiv(N * 32, T), T>>>(rowptr, csr, h, dis, b1, agg, N);

    // ---- layer 2 ----
    k_gemm64  <<<cdiv(N * 32, T), T>>>(agg, W2, h, N, 1);
    k_gather  <<<cdiv(N * 32, T), T>>>(rowptr, csr, h, dis, b2, out, N);
}

// round 12
// speedup vs baseline: 1.9467x; 1.9467x over previous
#include <cuda_runtime.h>
#include <stdint.h>

#define NN 100000
#define F  64
#define E_MAX 1700000

// ---- scratch (static __device__ arrays; no allocation allowed) ----
__device__ int   g_cnt[NN];          // in-degree (real edges only)
__device__ float g_dis[NN];          // deg^{-1/2} (incl. self loop)
__device__ int   g_rowptr[NN + 1];
__device__ int   g_cursor[NN];
__device__ int2  g_csr[E_MAX];       // {src, float_as_int(norm)} grouped by dst
__device__ float g_h[NN * F];        // linear output of current layer
__device__ float g_agg[NN * F];      // layer-1 aggregation result
__device__ int   g_is64;             // edge_index dtype flag

// ---------------------------------------------------------------------------
// K0: detect edge_index dtype. For nonnegative int64 (LE), every odd 32-bit
// word is 0. For random int32 indices, essentially never.
__global__ void k_detect(const unsigned int* __restrict__ w) {
    if (threadIdx.x == 0 && blockIdx.x == 0) {
        int is64 = 1;
        #pragma unroll 1
        for (int i = 1; i < 128; i += 2)
            if (w[i] != 0u) { is64 = 0; break; }
        g_is64 = is64;
    }
}

__device__ __forceinline__ int load_idx(const void* ei, long long elem, int is64) {
    if (is64) return (int)((const long long*)ei)[elem];
    return ((const int*)ei)[elem];
}

// K1: zero in-degree counters
__global__ void k_cnt_init(int* cnt, int n) {
    int i = blockIdx.x * blockDim.x + threadIdx.x;
    if (i < n) cnt[i] = 0;
}

// K2: in-degree histogram over real edges (dst row of edge_index [2,E])
__global__ void k_cnt_acc(const void* __restrict__ ei, int* cnt, int E) {
    int e = blockIdx.x * blockDim.x + threadIdx.x;
    if (e >= E) return;
    int d = load_idx(ei, (long long)E + e, g_is64);
    if ((unsigned)d < (unsigned)NN) atomicAdd(&cnt[d], 1);
}

// K3: dis = (cnt+1)^{-1/2}   (+1 self loop)
__global__ void k_dis(const int* __restrict__ cnt, float* dis, int n) {
    int i = blockIdx.x * blockDim.x + threadIdx.x;
    if (i < n) dis[i] = rsqrtf((float)cnt[i] + 1.0f);
}

// K4: tiled, COALESCED single-block exclusive scan: cnt -> rowptr (+cursor).
// Lane tid reads cnt[base+tid] each tile; block shfl-scan; carry in smem.
__global__ void k_scan(const int* __restrict__ cnt, int* __restrict__ rowptr,
                       int* __restrict__ cursor, int n) {
    __shared__ int warp_sums[32];
    __shared__ int carry_s;
    int tid  = threadIdx.x;
    int lane = tid & 31, warp = tid >> 5;
    if (tid == 0) carry_s = 0;
    __syncthreads();

    for (int base = 0; base < n; base += blockDim.x) {
        int i = base + tid;
        int v = (i < n) ? cnt[i] : 0;

        // warp-inclusive scan
        int s = v;
        #pragma unroll
        for (int o = 1; o < 32; o <<= 1) {
            int t = __shfl_up_sync(0xffffffffu, s, o);
            if (lane >= o) s += t;
        }
        if (lane == 31) warp_sums[warp] = s;
        __syncthreads();
        if (warp == 0) {
            int ws = warp_sums[lane];
            #pragma unroll
            for (int o = 1; o < 32; o <<= 1) {
                int t = __shfl_up_sync(0xffffffffu, ws, o);
                if (lane >= o) ws += t;
            }
            warp_sums[lane] = ws;     // inclusive across warps
        }
        __syncthreads();
        int incl = s + (warp > 0 ? warp_sums[warp - 1] : 0);
        int c = carry_s;
        if (i < n) {
            int e = c + incl - v;     // exclusive prefix
            rowptr[i] = e;
            cursor[i] = e;
        }
        __syncthreads();              // all reads of carry_s done
        if (tid == blockDim.x - 1) carry_s = c + incl;
        __syncthreads();
    }
    if (tid == 0) rowptr[n] = carry_s;
}

// K5: fill CSR — slot per edge via cursor atomic; store {src, norm}
__global__ void k_fill(const void* __restrict__ ei, const float* __restrict__ dis,
                       int* __restrict__ cursor, int2* __restrict__ csr, int E) {
    int e = blockIdx.x * blockDim.x + threadIdx.x;
    if (e >= E) return;
    int is64 = g_is64;
    int s = load_idx(ei, e, is64);
    int d = load_idx(ei, (long long)E + e, is64);
    if ((unsigned)s >= (unsigned)NN || (unsigned)d >= (unsigned)NN) return;
    float nm = dis[s] * dis[d];
    int slot = atomicAdd(&cursor[d], 1);
    csr[slot] = make_int2(s, __float_as_int(nm));
}

// ---------------------------------------------------------------------------
// GEMM: H[n,64] = act(X[n,64]) @ W[64,64]. Warp-per-row, W in smem,
// x row in registers (float2/lane), shfl broadcast.
__global__ void k_gemm64(const float* __restrict__ X, const float* __restrict__ Wg,
                         float* __restrict__ H, int n, int do_relu) {
    __shared__ __align__(16) float Ws[F * F];
    for (int i = threadIdx.x; i < F * F; i += blockDim.x) Ws[i] = Wg[i];
    __syncthreads();

    int warp = (blockIdx.x * blockDim.x + threadIdx.x) >> 5;
    int lane = threadIdx.x & 31;
    if (warp >= n) return;

    float2 xv = ((const float2*)(X + (size_t)warp * F))[lane];
    if (do_relu) { xv.x = fmaxf(xv.x, 0.0f); xv.y = fmaxf(xv.y, 0.0f); }

    float a0 = 0.0f, a1 = 0.0f;
#pragma unroll
    for (int k = 0; k < F; k++) {
        float xk = __shfl_sync(0xffffffffu, (k & 1) ? xv.y : xv.x, k >> 1);
        float2 w = ((const float2*)(Ws + k * F))[lane];
        a0 = fmaf(xk, w.x, a0);
        a1 = fmaf(xk, w.y, a1);
    }
    ((float2*)(H + (size_t)warp * F))[lane] = make_float2(a0, a1);
}

// ---------------------------------------------------------------------------
// Gather-aggregate: warp per dst node. acc = H[node]*dis^2 + b, then
// += sum over incoming edges of H[src]*norm. Register accumulation, no atomics.
__global__ void k_gather(const int* __restrict__ rowptr, const int2* __restrict__ csr,
                         const float* __restrict__ H, const float* __restrict__ dis,
                         const float* __restrict__ b, float* __restrict__ Agg, int n) {
    int node = (blockIdx.x * blockDim.x + threadIdx.x) >> 5;
    int lane = threadIdx.x & 31;
    if (node >= n) return;

    int beg = rowptr[node];
    int end = rowptr[node + 1];

    float dd = dis[node];
    float sl = dd * dd;
    float2 hs = ((const float2*)(H + (size_t)node * F))[lane];
    float2 bb = ((const float2*)b)[lane];
    float ax = fmaf(hs.x, sl, bb.x);
    float ay = fmaf(hs.y, sl, bb.y);

    int j = beg;
    for (; j + 3 < end; j += 4) {
        int2 e0 = __ldg(&csr[j]);
        int2 e1 = __ldg(&csr[j + 1]);
        int2 e2 = __ldg(&csr[j + 2]);
        int2 e3 = __ldg(&csr[j + 3]);
        float2 v0 = ((const float2*)(H + (size_t)e0.x * F))[lane];
        float2 v1 = ((const float2*)(H + (size_t)e1.x * F))[lane];
        float2 v2 = ((const float2*)(H + (size_t)e2.x * F))[lane];
        float2 v3 = ((const float2*)(H + (size_t)e3.x * F))[lane];
        ax = fmaf(v0.x, __int_as_float(e0.y), ax);
        ay = fmaf(v0.y, __int_as_float(e0.y), ay);
        ax = fmaf(v1.x, __int_as_float(e1.y), ax);
        ay = fmaf(v1.y, __int_as_float(e1.y), ay);
        ax = fmaf(v2.x, __int_as_float(e2.y), ax);
        ay = fmaf(v2.y, __int_as_float(e2.y), ay);
        ax = fmaf(v3.x, __int_as_float(e3.y), ax);
        ay = fmaf(v3.y, __int_as_float(e3.y), ay);
    }
    for (; j < end; j++) {
        int2 e0 = __ldg(&csr[j]);
        float2 v0 = ((const float2*)(H + (size_t)e0.x * F))[lane];
        ax = fmaf(v0.x, __int_as_float(e0.y), ax);
        ay = fmaf(v0.y, __int_as_float(e0.y), ay);
    }
    ((float2*)(Agg + (size_t)node * F))[lane] = make_float2(ax, ay);
}

// ---------------------------------------------------------------------------
static inline int cdiv(int a, int b) { return (a + b - 1) / b; }

extern "C" void kernel_launch(void* const* d_in, const int* in_sizes, int n_in,
                              void* d_out, int out_size) {
    const float* x  = (const float*)d_in[0];
    const void*  ei = d_in[1];
    const float* W1 = (const float*)d_in[2];
    const float* b1 = (const float*)d_in[3];
    const float* W2 = (const float*)d_in[4];
    const float* b2 = (const float*)d_in[5];
    float*       out = (float*)d_out;

    const int N = in_sizes[0] / F;        // 100000
    const int E = in_sizes[1] / 2;        // 1600000

    int *cnt, *rowptr, *cursor;
    int2 *csr;
    float *dis, *h, *agg;
    cudaGetSymbolAddress((void**)&cnt,    g_cnt);
    cudaGetSymbolAddress((void**)&dis,    g_dis);
    cudaGetSymbolAddress((void**)&rowptr, g_rowptr);
    cudaGetSymbolAddress((void**)&cursor, g_cursor);
    cudaGetSymbolAddress((void**)&csr,    g_csr);
    cudaGetSymbolAddress((void**)&h,      g_h);
    cudaGetSymbolAddress((void**)&agg,    g_agg);

    const int T = 256;

    // ---- preprocessing (once per call, reused by both layers) ----
    k_detect  <<<1, 32>>>((const unsigned int*)ei);
    k_cnt_init<<<cdiv(N, T), T>>>(cnt, N);
    k_cnt_acc <<<cdiv(E, T), T>>>(ei, cnt, E);
    k_dis     <<<cdiv(N, T), T>>>(cnt, dis, N);
    k_scan    <<<1, 1024>>>(cnt, rowptr, cursor, N);
    k_fill    <<<cdiv(E, T), T>>>(ei, dis, cursor, csr, E);

    // ---- layer 1 ----
    k_gemm64  <<<cdiv(N * 32, T), T>>>(x, W1, h, N, 0);
    k_gather  <<<cdiv(N * 32, T), T>>>(rowptr, csr, h, dis, b1, agg, N);

    // ---- layer 2 ----
    k_gemm64  <<<cdiv(N * 32, T), T>>>(agg, W2, h, N, 1);
    k_gather  <<<cdiv(N * 32, T), T>>>(rowptr, csr, h, dis, b2, out, N);
}

// round 13
// speedup vs baseline: 2.0537x; 1.0549x over previous
#include <cuda_runtime.h>
#include <stdint.h>

#define NN 100000
#define F  64
#define E_MAX 1700000

// ---- scratch (static __device__ arrays; no allocation allowed) ----
__device__ int   g_cnt[NN];          // in-degree (real edges only)
__device__ float g_dis[NN];          // deg^{-1/2} (incl. self loop)
__device__ int   g_rowptr[NN + 1];
__device__ int   g_cursor[NN];
__device__ int2  g_csr[E_MAX];       // {src, float_as_int(norm)} grouped by dst
__device__ float g_h[NN * F];        // linear output of current layer
__device__ float g_agg[NN * F];      // layer-1 aggregation result
__device__ int   g_is64;             // edge_index dtype flag

// ---------------------------------------------------------------------------
// K0: detect edge_index dtype. For nonnegative int64 (LE), every odd 32-bit
// word is 0. For random int32 indices, essentially never.
__global__ void k_detect(const unsigned int* __restrict__ w) {
    if (threadIdx.x == 0 && blockIdx.x == 0) {
        int is64 = 1;
        #pragma unroll 1
        for (int i = 1; i < 128; i += 2)
            if (w[i] != 0u) { is64 = 0; break; }
        g_is64 = is64;
    }
}

__device__ __forceinline__ int load_idx(const void* ei, long long elem, int is64) {
    if (is64) return (int)((const long long*)ei)[elem];
    return ((const int*)ei)[elem];
}

// K1: in-degree histogram over real edges (dst row of edge_index [2,E])
__global__ void k_cnt_acc(const void* __restrict__ ei, int* cnt, int E) {
    int e = blockIdx.x * blockDim.x + threadIdx.x;
    if (e >= E) return;
    int d = load_idx(ei, (long long)E + e, g_is64);
    if ((unsigned)d < (unsigned)NN) atomicAdd(&cnt[d], 1);
}

// K2: dis = (cnt+1)^{-1/2}   (+1 self loop)
__global__ void k_dis(const int* __restrict__ cnt, float* dis, int n) {
    int i = blockIdx.x * blockDim.x + threadIdx.x;
    if (i < n) dis[i] = rsqrtf((float)cnt[i] + 1.0f);
}

// K3: tiled, coalesced single-block exclusive scan: cnt -> rowptr (+cursor).
__global__ void k_scan(const int* __restrict__ cnt, int* __restrict__ rowptr,
                       int* __restrict__ cursor, int n) {
    __shared__ int warp_sums[32];
    __shared__ int carry_s;
    int tid  = threadIdx.x;
    int lane = tid & 31, warp = tid >> 5;
    if (tid == 0) carry_s = 0;
    __syncthreads();

    for (int base = 0; base < n; base += blockDim.x) {
        int i = base + tid;
        int v = (i < n) ? cnt[i] : 0;

        int s = v;
        #pragma unroll
        for (int o = 1; o < 32; o <<= 1) {
            int t = __shfl_up_sync(0xffffffffu, s, o);
            if (lane >= o) s += t;
        }
        if (lane == 31) warp_sums[warp] = s;
        __syncthreads();
        if (warp == 0) {
            int ws = warp_sums[lane];
            #pragma unroll
            for (int o = 1; o < 32; o <<= 1) {
                int t = __shfl_up_sync(0xffffffffu, ws, o);
                if (lane >= o) ws += t;
            }
            warp_sums[lane] = ws;
        }
        __syncthreads();
        int incl = s + (warp > 0 ? warp_sums[warp - 1] : 0);
        int c = carry_s;
        if (i < n) {
            int e = c + incl - v;
            rowptr[i] = e;
            cursor[i] = e;
        }
        __syncthreads();
        if (tid == blockDim.x - 1) carry_s = c + incl;
        __syncthreads();
    }
    if (tid == 0) rowptr[n] = carry_s;
}

// K4: fill CSR — slot per edge via cursor atomic; store {src, norm}
__global__ void k_fill(const void* __restrict__ ei, const float* __restrict__ dis,
                       int* __restrict__ cursor, int2* __restrict__ csr, int E) {
    int e = blockIdx.x * blockDim.x + threadIdx.x;
    if (e >= E) return;
    int is64 = g_is64;
    int s = load_idx(ei, e, is64);
    int d = load_idx(ei, (long long)E + e, is64);
    if ((unsigned)s >= (unsigned)NN || (unsigned)d >= (unsigned)NN) return;
    float nm = dis[s] * dis[d];
    int slot = atomicAdd(&cursor[d], 1);
    csr[slot] = make_int2(s, __float_as_int(nm));
}

// ---------------------------------------------------------------------------
// GEMM: H[n,64] = act(X[n,64]) @ W[64,64]. Warp-per-row, W in smem,
// x row in registers (float2/lane), shfl broadcast.
__global__ void k_gemm64(const float* __restrict__ X, const float* __restrict__ Wg,
                         float* __restrict__ H, int n, int do_relu) {
    __shared__ __align__(16) float Ws[F * F];
    for (int i = threadIdx.x; i < F * F; i += blockDim.x) Ws[i] = Wg[i];
    __syncthreads();

    int warp = (blockIdx.x * blockDim.x + threadIdx.x) >> 5;
    int lane = threadIdx.x & 31;
    if (warp >= n) return;

    float2 xv = ((const float2*)(X + (size_t)warp * F))[lane];
    if (do_relu) { xv.x = fmaxf(xv.x, 0.0f); xv.y = fmaxf(xv.y, 0.0f); }

    float a0 = 0.0f, a1 = 0.0f;
#pragma unroll
    for (int k = 0; k < F; k++) {
        float xk = __shfl_sync(0xffffffffu, (k & 1) ? xv.y : xv.x, k >> 1);
        float2 w = ((const float2*)(Ws + k * F))[lane];
        a0 = fmaf(xk, w.x, a0);
        a1 = fmaf(xk, w.y, a1);
    }
    ((float2*)(H + (size_t)warp * F))[lane] = make_float2(a0, a1);
}

// ---------------------------------------------------------------------------
// Gather-aggregate v2: warp per dst node.
// One coalesced 32-wide csr load covers up to 32 incoming edges; {src,norm}
// broadcast from registers via shfl, so the H-row gathers are the ONLY loads
// in the loop and are mutually independent (deep MLP, no csr->H chain).
__global__ void __launch_bounds__(256) k_gather(
        const int* __restrict__ rowptr, const int2* __restrict__ csr,
        const float* __restrict__ H, const float* __restrict__ dis,
        const float* __restrict__ b, float* __restrict__ Agg, int n) {
    int node = (blockIdx.x * blockDim.x + threadIdx.x) >> 5;
    int lane = threadIdx.x & 31;
    if (node >= n) return;

    int beg = rowptr[node];
    int end = rowptr[node + 1];

    float dd = dis[node];
    float sl = dd * dd;
    float2 hs = ((const float2*)(H + (size_t)node * F))[lane];
    float2 bb = ((const float2*)b)[lane];
    float ax = fmaf(hs.x, sl, bb.x);
    float ay = fmaf(hs.y, sl, bb.y);

    #pragma unroll 1
    for (int base = beg; base < end; base += 32) {
        int m = end - base;
        if (m > 32) m = 32;
        int2 e = make_int2(0, 0);
        if (lane < m) e = __ldg(&csr[base + lane]);

        int k = 0;
        #pragma unroll 1
        for (; k + 3 < m; k += 4) {
            int   s0 = __shfl_sync(0xffffffffu, e.x, k);
            int   s1 = __shfl_sync(0xffffffffu, e.x, k + 1);
            int   s2 = __shfl_sync(0xffffffffu, e.x, k + 2);
            int   s3 = __shfl_sync(0xffffffffu, e.x, k + 3);
            float n0 = __int_as_float(__shfl_sync(0xffffffffu, e.y, k));
            float n1 = __int_as_float(__shfl_sync(0xffffffffu, e.y, k + 1));
            float n2 = __int_as_float(__shfl_sync(0xffffffffu, e.y, k + 2));
            float n3 = __int_as_float(__shfl_sync(0xffffffffu, e.y, k + 3));
            float2 v0 = ((const float2*)(H + (size_t)s0 * F))[lane];
            float2 v1 = ((const float2*)(H + (size_t)s1 * F))[lane];
            float2 v2 = ((const float2*)(H + (size_t)s2 * F))[lane];
            float2 v3 = ((const float2*)(H + (size_t)s3 * F))[lane];
            ax = fmaf(v0.x, n0, ax);  ay = fmaf(v0.y, n0, ay);
            ax = fmaf(v1.x, n1, ax);  ay = fmaf(v1.y, n1, ay);
            ax = fmaf(v2.x, n2, ax);  ay = fmaf(v2.y, n2, ay);
            ax = fmaf(v3.x, n3, ax);  ay = fmaf(v3.y, n3, ay);
        }
        #pragma unroll 1
        for (; k < m; k++) {
            int   s0 = __shfl_sync(0xffffffffu, e.x, k);
            float n0 = __int_as_float(__shfl_sync(0xffffffffu, e.y, k));
            float2 v0 = ((const float2*)(H + (size_t)s0 * F))[lane];
            ax = fmaf(v0.x, n0, ax);  ay = fmaf(v0.y, n0, ay);
        }
    }
    ((float2*)(Agg + (size_t)node * F))[lane] = make_float2(ax, ay);
}

// ---------------------------------------------------------------------------
static inline int cdiv(int a, int b) { return (a + b - 1) / b; }

extern "C" void kernel_launch(void* const* d_in, const int* in_sizes, int n_in,
                              void* d_out, int out_size) {
    const float* x  = (const float*)d_in[0];
    const void*  ei = d_in[1];
    const float* W1 = (const float*)d_in[2];
    const float* b1 = (const float*)d_in[3];
    const float* W2 = (const float*)d_in[4];
    const float* b2 = (const float*)d_in[5];
    float*       out = (float*)d_out;

    const int N = in_sizes[0] / F;        // 100000
    const int E = in_sizes[1] / 2;        // 1600000

    int *cnt, *rowptr, *cursor;
    int2 *csr;
    float *dis, *h, *agg;
    cudaGetSymbolAddress((void**)&cnt,    g_cnt);
    cudaGetSymbolAddress((void**)&dis,    g_dis);
    cudaGetSymbolAddress((void**)&rowptr, g_rowptr);
    cudaGetSymbolAddress((void**)&cursor, g_cursor);
    cudaGetSymbolAddress((void**)&csr,    g_csr);
    cudaGetSymbolAddress((void**)&h,      g_h);
    cudaGetSymbolAddress((void**)&agg,    g_agg);

    const int T = 256;

    // ---- preprocessing (once per call, reused by both layers) ----
    k_detect <<<1, 32>>>((const unsigned int*)ei);
    cudaMemsetAsync(cnt, 0, (size_t)N * sizeof(int));
    k_cnt_acc<<<cdiv(E, T), T>>>(ei, cnt, E);
    k_dis    <<<cdiv(N, T), T>>>(cnt, dis, N);
    k_scan   <<<1, 1024>>>(cnt, rowptr, cursor, N);
    k_fill   <<<cdiv(E, T), T>>>(ei, dis, cursor, csr, E);

    // ---- layer 1 ----
    k_gemm64 <<<cdiv(N * 32, T), T>>>(x, W1, h, N, 0);
    k_gather <<<cdiv(N * 32, T), T>>>(rowptr, csr, h, dis, b1, agg, N);

    // ---- layer 2 ----
    k_gemm64 <<<cdiv(N * 32, T), T>>>(agg, W2, h, N, 1);
    k_gather <<<cdiv(N * 32, T), T>>>(rowptr, csr, h, dis, b2, out, N);
}

// round 16
// speedup vs baseline: 2.4789x; 1.2070x over previous
#include <cuda_runtime.h>
#include <stdint.h>

#define NN 100000
#define F  64
#define E_MAX 1700000
#define SCAN_T 1024
#define SCAN_B ((NN + SCAN_T - 1) / SCAN_T)   // 98 tiles

// ---- scratch (static __device__ arrays; no allocation allowed) ----
__device__ int   g_cnt[NN];          // in-degree (real edges only)
__device__ float g_dis[NN];          // deg^{-1/2} (incl. self loop)
__device__ int   g_rowptr[NN + 1];
__device__ int   g_cursor[NN];
__device__ int   g_blocksum[SCAN_B];
__device__ int2  g_csr[E_MAX];       // {src, float_as_int(norm)} grouped by dst
__device__ float g_h[NN * F];        // linear output of current layer
__device__ float g_agg[NN * F];      // layer-1 aggregation result
__device__ int   g_is64;             // edge_index dtype flag

// ---------------------------------------------------------------------------
// K0: detect edge_index dtype. For nonnegative int64 (LE), every odd 32-bit
// word is 0. For random int32 indices, essentially never.
__global__ void k_detect(const unsigned int* __restrict__ w) {
    if (threadIdx.x == 0 && blockIdx.x == 0) {
        int is64 = 1;
        #pragma unroll 1
        for (int i = 1; i < 128; i += 2)
            if (w[i] != 0u) { is64 = 0; break; }
        g_is64 = is64;
    }
}

__device__ __forceinline__ int load_idx(const void* ei, long long elem, int is64) {
    if (is64) return (int)((const long long*)ei)[elem];
    return ((const int*)ei)[elem];
}

// K1: in-degree histogram over real edges (dst row of edge_index [2,E])
__global__ void k_cnt_acc(const void* __restrict__ ei, int* cnt, int E) {
    int e = blockIdx.x * blockDim.x + threadIdx.x;
    if (e >= E) return;
    int d = load_idx(ei, (long long)E + e, g_is64);
    if ((unsigned)d < (unsigned)NN) atomicAdd(&cnt[d], 1);
}

// K2: dis = (cnt+1)^{-1/2}   (+1 self loop)
__global__ void k_dis(const int* __restrict__ cnt, float* dis, int n) {
    int i = blockIdx.x * blockDim.x + threadIdx.x;
    if (i < n) dis[i] = rsqrtf((float)cnt[i] + 1.0f);
}

// ---------------------------------------------------------------------------
// Multi-block exclusive scan of cnt -> rowptr/cursor. 3 phases.

// P1: per-tile sums
__global__ void k_blocksum(const int* __restrict__ cnt, int* __restrict__ bsum, int n) {
    __shared__ int wsum[32];
    int i = blockIdx.x * SCAN_T + threadIdx.x;
    int v = (i < n) ? cnt[i] : 0;
    int lane = threadIdx.x & 31, warp = threadIdx.x >> 5;
    #pragma unroll
    for (int o = 16; o > 0; o >>= 1) v += __shfl_down_sync(0xffffffffu, v, o);
    if (lane == 0) wsum[warp] = v;
    __syncthreads();
    if (warp == 0) {
        int t = wsum[lane];
        #pragma unroll
        for (int o = 16; o > 0; o >>= 1) t += __shfl_down_sync(0xffffffffu, t, o);
        if (lane == 0) bsum[blockIdx.x] = t;
    }
}

// P2: exclusive scan of the (<=128) tile sums in one small block; also writes total
__global__ void k_scan_base(int* __restrict__ bsum, int* __restrict__ rowptr, int nb, int n) {
    __shared__ int wsum[4];
    int tid = threadIdx.x;                       // 128 threads
    int v = (tid < nb) ? bsum[tid] : 0;
    int lane = tid & 31, warp = tid >> 5;
    int s = v;
    #pragma unroll
    for (int o = 1; o < 32; o <<= 1) {
        int t = __shfl_up_sync(0xffffffffu, s, o);
        if (lane >= o) s += t;
    }
    if (lane == 31) wsum[warp] = s;
    __syncthreads();
    int woff = 0;
    #pragma unroll
    for (int w = 0; w < 4; w++) if (w < warp) woff += wsum[w];
    int incl = s + woff;
    if (tid < nb) bsum[tid] = incl - v;          // exclusive tile offset
    if (tid == nb - 1) rowptr[n] = incl;         // grand total
}

// P3: in-tile exclusive scan + tile offset
__global__ void k_scan_tiles(const int* __restrict__ cnt, const int* __restrict__ bsum,
                             int* __restrict__ rowptr, int* __restrict__ cursor, int n) {
    __shared__ int wsum[32];
    int i = blockIdx.x * SCAN_T + threadIdx.x;
    int v = (i < n) ? cnt[i] : 0;
    int lane = threadIdx.x & 31, warp = threadIdx.x >> 5;
    int s = v;
    #pragma unroll
    for (int o = 1; o < 32; o <<= 1) {
        int t = __shfl_up_sync(0xffffffffu, s, o);
        if (lane >= o) s += t;
    }
    if (lane == 31) wsum[warp] = s;
    __syncthreads();
    if (warp == 0) {
        int ws = wsum[lane];
        #pragma unroll
        for (int o = 1; o < 32; o <<= 1) {
            int t = __shfl_up_sync(0xffffffffu, ws, o);
            if (lane >= o) ws += t;
        }
        wsum[lane] = ws;
    }
    __syncthreads();
    int excl = s - v + (warp > 0 ? wsum[warp - 1] : 0) + bsum[blockIdx.x];
    if (i < n) {
        rowptr[i] = excl;
        cursor[i] = excl;
    }
}

// K4: fill CSR — slot per edge via cursor atomic; store {src, norm}
__global__ void k_fill(const void* __restrict__ ei, const float* __restrict__ dis,
                       int* __restrict__ cursor, int2* __restrict__ csr, int E) {
    int e = blockIdx.x * blockDim.x + threadIdx.x;
    if (e >= E) return;
    int is64 = g_is64;
    int s = load_idx(ei, e, is64);
    int d = load_idx(ei, (long long)E + e, is64);
    if ((unsigned)s >= (unsigned)NN || (unsigned)d >= (unsigned)NN) return;
    float nm = dis[s] * dis[d];
    int slot = atomicAdd(&cursor[d], 1);
    csr[slot] = make_int2(s, __float_as_int(nm));
}

// ---------------------------------------------------------------------------
// GEMM: H[n,64] = act(X[n,64]) @ W[64,64]. Warp-per-row, W in smem,
// x row in registers (float2/lane), shfl broadcast.
__global__ void k_gemm64(const float* __restrict__ X, const float* __restrict__ Wg,
                         float* __restrict__ H, int n, int do_relu) {
    __shared__ __align__(16) float Ws[F * F];
    for (int i = threadIdx.x; i < F * F; i += blockDim.x) Ws[i] = Wg[i];
    __syncthreads();

    int warp = (blockIdx.x * blockDim.x + threadIdx.x) >> 5;
    int lane = threadIdx.x & 31;
    if (warp >= n) return;

    float2 xv = ((const float2*)(X + (size_t)warp * F))[lane];
    if (do_relu) { xv.x = fmaxf(xv.x, 0.0f); xv.y = fmaxf(xv.y, 0.0f); }

    float a0 = 0.0f, a1 = 0.0f;
#pragma unroll
    for (int k = 0; k < F; k++) {
        float xk = __shfl_sync(0xffffffffu, (k & 1) ? xv.y : xv.x, k >> 1);
        float2 w = ((const float2*)(Ws + k * F))[lane];
        a0 = fmaf(xk, w.x, a0);
        a1 = fmaf(xk, w.y, a1);
    }
    ((float2*)(H + (size_t)warp * F))[lane] = make_float2(a0, a1);
}

// ---------------------------------------------------------------------------
// Gather-aggregate: warp per dst node. One coalesced 32-wide csr load per
// chunk; {src,norm} broadcast via shfl; H-row gathers independent.
__global__ void __launch_bounds__(256) k_gather(
        const int* __restrict__ rowptr, const int2* __restrict__ csr,
        const float* __restrict__ H, const float* __restrict__ dis,
        const float* __restrict__ b, float* __restrict__ Agg, int n) {
    int node = (blockIdx.x * blockDim.x + threadIdx.x) >> 5;
    int lane = threadIdx.x & 31;
    if (node >= n) return;

    int beg = rowptr[node];
    int end = rowptr[node + 1];

    float dd = dis[node];
    float sl = dd * dd;
    float2 hs = ((const float2*)(H + (size_t)node * F))[lane];
    float2 bb = ((const float2*)b)[lane];
    float ax = fmaf(hs.x, sl, bb.x);
    float ay = fmaf(hs.y, sl, bb.y);

    #pragma unroll 1
    for (int base = beg; base < end; base += 32) {
        int m = end - base;
        if (m > 32) m = 32;
        int2 e = make_int2(0, 0);
        if (lane < m) e = __ldg(&csr[base + lane]);

        int k = 0;
        #pragma unroll 1
        for (; k + 3 < m; k += 4) {
            int   s0 = __shfl_sync(0xffffffffu, e.x, k);
            int   s1 = __shfl_sync(0xffffffffu, e.x, k + 1);
            int   s2 = __shfl_sync(0xffffffffu, e.x, k + 2);
            int   s3 = __shfl_sync(0xffffffffu, e.x, k + 3);
            float n0 = __int_as_float(__shfl_sync(0xffffffffu, e.y, k));
            float n1 = __int_as_float(__shfl_sync(0xffffffffu, e.y, k + 1));
            float n2 = __int_as_float(__shfl_sync(0xffffffffu, e.y, k + 2));
            float n3 = __int_as_float(__shfl_sync(0xffffffffu, e.y, k + 3));
            float2 v0 = ((const float2*)(H + (size_t)s0 * F))[lane];
            float2 v1 = ((const float2*)(H + (size_t)s1 * F))[lane];
            float2 v2 = ((const float2*)(H + (size_t)s2 * F))[lane];
            float2 v3 = ((const float2*)(H + (size_t)s3 * F))[lane];
            ax = fmaf(v0.x, n0, ax);  ay = fmaf(v0.y, n0, ay);
            ax = fmaf(v1.x, n1, ax);  ay = fmaf(v1.y, n1, ay);
            ax = fmaf(v2.x, n2, ax);  ay = fmaf(v2.y, n2, ay);
            ax = fmaf(v3.x, n3, ax);  ay = fmaf(v3.y, n3, ay);
        }
        #pragma unroll 1
        for (; k < m; k++) {
            int   s0 = __shfl_sync(0xffffffffu, e.x, k);
            float n0 = __int_as_float(__shfl_sync(0xffffffffu, e.y, k));
            float2 v0 = ((const float2*)(H + (size_t)s0 * F))[lane];
            ax = fmaf(v0.x, n0, ax);  ay = fmaf(v0.y, n0, ay);
        }
    }
    ((float2*)(Agg + (size_t)node * F))[lane] = make_float2(ax, ay);
}

// ---------------------------------------------------------------------------
static inline int cdiv(int a, int b) { return (a + b - 1) / b; }

extern "C" void kernel_launch(void* const* d_in, const int* in_sizes, int n_in,
                              void* d_out, int out_size) {
    const float* x  = (const float*)d_in[0];
    const void*  ei = d_in[1];
    const float* W1 = (const float*)d_in[2];
    const float* b1 = (const float*)d_in[3];
    const float* W2 = (const float*)d_in[4];
    const float* b2 = (const float*)d_in[5];
    float*       out = (float*)d_out;

    const int N = in_sizes[0] / F;        // 100000
    const int E = in_sizes[1] / 2;        // 1600000
    const int NB = cdiv(N, SCAN_T);       // 98

    int *cnt, *rowptr, *cursor, *bsum;
    int2 *csr;
    float *dis, *h, *agg;
    cudaGetSymbolAddress((void**)&cnt,    g_cnt);
    cudaGetSymbolAddress((void**)&dis,    g_dis);
    cudaGetSymbolAddress((void**)&rowptr, g_rowptr);
    cudaGetSymbolAddress((void**)&cursor, g_cursor);
    cudaGetSymbolAddress((void**)&bsum,   g_blocksum);
    cudaGetSymbolAddress((void**)&csr,    g_csr);
    cudaGetSymbolAddress((void**)&h,      g_h);
    cudaGetSymbolAddress((void**)&agg,    g_agg);

    const int T = 256;

    // ---- preprocessing (once per call, reused by both layers) ----
    k_detect    <<<1, 32>>>((const unsigned int*)ei);
    cudaMemsetAsync(cnt, 0, (size_t)N * sizeof(int));
    k_cnt_acc   <<<cdiv(E, T), T>>>(ei, cnt, E);
    k_dis       <<<cdiv(N, T), T>>>(cnt, dis, N);
    k_blocksum  <<<NB, SCAN_T>>>(cnt, bsum, N);
    k_scan_base <<<1, 128>>>(bsum, rowptr, NB, N);
    k_scan_tiles<<<NB, SCAN_T>>>(cnt, bsum, rowptr, cursor, N);
    k_fill      <<<cdiv(E, T), T>>>(ei, dis, cursor, csr, E);

    // ---- layer 1 ----
    k_gemm64 <<<cdiv(N * 32, T), T>>>(x, W1, h, N, 0);
    k_gather <<<cdiv(N * 32, T), T>>>(rowptr, csr, h, dis, b1, agg, N);

    // ---- layer 2 ----
    k_gemm64 <<<cdiv(N * 32, T), T>>>(agg, W2, h, N, 1);
    k_gather <<<cdiv(N * 32, T), T>>>(rowptr, csr, h, dis, b2, out, N);
}